// round 1
// baseline (speedup 1.0000x reference)
#include <cuda_runtime.h>
#include <cuda_bf16.h>
#include <cfloat>

#define LEAKF 0.2f

// ---------------- device scratch (no allocation allowed) ----------------
__device__ float g_d[4L * 4096 * 4096];   // 256 MB distance matrices
__device__ float g_cat[16384L * 512];     // x1|x2|x3|x4 concat, ld=512
__device__ float g_q[16384L * 256];
__device__ float g_p[16384L * 256];
__device__ float g_x2[16384];
__device__ int   g_idx[16384L * 20];
__device__ float g_local[16384L * 512];
__device__ float g_emb[16384L * 1024];
__device__ float g_part[64L * 1024];
__device__ float g_glob[4L * 1024];
__device__ float g_gh[4L * 256];
__device__ float g_h1[16384L * 256];
__device__ float g_h2[16384L * 256];
__device__ float g_wd[256 * 128];

__device__ __forceinline__ float lrelu(float v) { return v > 0.f ? v : LEAKF * v; }

// ---------------- generic tiled fp32 GEMM with fused epilogues ----------------
// Y[m][n] = sum_k X[m][k] * W[n][k]   (both row-major, arbitrary ld, batched via z)
// MODE 0: Y = acc
// MODE 1: Y = leaky(acc*s[n] + b[n])
// MODE 2: Y = x2[m] + x2[n] - 2*acc          (pairwise sq. distance; aux=x2, per-z)
// MODE 3: Y = leaky(s[n]*(acc + aux[(m>>12)*auxS + n]) + b[n])   (h1 with global add)
// MODE 4: Y = acc + b[n]
template<int MODE>
__global__ void gemm_k(const float* __restrict__ X, int ldx, long xbs,
                       const float* __restrict__ W, int ldw, long wbs,
                       float* __restrict__ Y, int ldy, long ybs,
                       int M, int K, int NO,
                       const float* __restrict__ sv,
                       const float* __restrict__ bv,
                       const float* __restrict__ aux, int auxS)
{
    __shared__ float Xs[16][64];
    __shared__ float Ws[16][68];
    int z = blockIdx.z;
    const float* Xb = X + (long)z * xbs;
    const float* Wb = W + (long)z * wbs;
    float* Yb = Y + (long)z * ybs;
    int row0 = blockIdx.y * 64;
    int col0 = blockIdx.x * 64;
    int tid = threadIdx.x;
    int tx = tid & 15, ty = tid >> 4;
    int lm = tid >> 2;
    int lk4 = (tid & 3) * 4;

    float acc[4][4] = {};

    for (int k0 = 0; k0 < K; k0 += 16) {
#pragma unroll
        for (int j = 0; j < 4; j++) {
            int kk = lk4 + j;
            int gm = row0 + lm, gk = k0 + kk;
            Xs[kk][lm] = (gm < M && gk < K) ? Xb[(long)gm * ldx + gk] : 0.f;
        }
#pragma unroll
        for (int j = 0; j < 4; j++) {
            int kk = lk4 + j;
            int gn = col0 + lm, gk = k0 + kk;
            Ws[kk][lm] = (gn < NO && gk < K) ? Wb[(long)gn * ldw + gk] : 0.f;
        }
        __syncthreads();
#pragma unroll
        for (int kk = 0; kk < 16; kk++) {
            float a[4], b[4];
#pragma unroll
            for (int i = 0; i < 4; i++) a[i] = Xs[kk][ty * 4 + i];
#pragma unroll
            for (int j = 0; j < 4; j++) b[j] = Ws[kk][tx * 4 + j];
#pragma unroll
            for (int i = 0; i < 4; i++)
#pragma unroll
                for (int j = 0; j < 4; j++)
                    acc[i][j] = fmaf(a[i], b[j], acc[i][j]);
        }
        __syncthreads();
    }

#pragma unroll
    for (int i = 0; i < 4; i++) {
        int gm = row0 + ty * 4 + i;
        if (gm >= M) continue;
#pragma unroll
        for (int j = 0; j < 4; j++) {
            int gn = col0 + tx * 4 + j;
            if (gn >= NO) continue;
            float v = acc[i][j];
            if (MODE == 1) v = lrelu(v * sv[gn] + bv[gn]);
            else if (MODE == 2) {
                const float* x2 = aux + (long)z * auxS;
                v = x2[gm] + x2[gn] - 2.f * v;
            } else if (MODE == 3) {
                int b = gm >> 12;
                v = lrelu(sv[gn] * (v + aux[b * auxS + gn]) + bv[gn]);
            } else if (MODE == 4) v = v + bv[gn];
            Yb[(long)gm * ldy + gn] = v;
        }
    }
}

// ---------------- squared norms (warp per row) ----------------
__global__ void sqnorm_k(const float* __restrict__ X, int ldx, int C, float* __restrict__ x2)
{
    int warp = (blockIdx.x * blockDim.x + threadIdx.x) >> 5;
    int lane = threadIdx.x & 31;
    if (warp >= 16384) return;
    const float* xr = X + (long)warp * ldx;
    float s = 0.f;
    for (int c = lane; c < C; c += 32) { float v = xr[c]; s = fmaf(v, v, s); }
#pragma unroll
    for (int off = 16; off; off >>= 1) s += __shfl_down_sync(0xffffffffu, s, off);
    if (lane == 0) x2[warp] = s;
}

// ---------------- top-20 smallest (iterative argmin, lowest-index tiebreak) ----------------
__global__ void topk_k(const float* __restrict__ D, int* __restrict__ idx)
{
    __shared__ float vals[4096];
    __shared__ float rv[128];
    __shared__ int   ri[128];
    long r = blockIdx.x;
    const float* drow = D + r * 4096;
    int tid = threadIdx.x;
    for (int j = tid; j < 4096; j += 128) vals[j] = drow[j];
    __syncthreads();
    for (int t = 0; t < 20; t++) {
        float best = FLT_MAX; int bi = 0x7fffffff;
        for (int j = tid; j < 4096; j += 128) {
            float v = vals[j];
            if (v < best) { best = v; bi = j; }
        }
        rv[tid] = best; ri[tid] = bi;
        __syncthreads();
        for (int s = 64; s > 0; s >>= 1) {
            if (tid < s) {
                float v2 = rv[tid + s]; int i2 = ri[tid + s];
                if (v2 < rv[tid] || (v2 == rv[tid] && i2 < ri[tid])) { rv[tid] = v2; ri[tid] = i2; }
            }
            __syncthreads();
        }
        if (tid == 0) { idx[r * 20 + t] = ri[0]; vals[ri[0]] = FLT_MAX; }
        __syncthreads();
    }
}

// ---------------- weight split:  wd[o][c] = w[o][C+c] - w[o][c] ----------------
__global__ void wdiff_k(const float* __restrict__ w, int C, int O, float* __restrict__ wd)
{
    int i = blockIdx.x * blockDim.x + threadIdx.x;
    if (i >= O * C) return;
    int o = i / C, c = i - o * C;
    wd[i] = w[o * 2 * C + C + c] - w[o * 2 * C + c];
}

// ---------------- edge gather + max + BN + leaky ----------------
__global__ void combine_k(const float* __restrict__ q, const float* __restrict__ p, int O,
                          const int* __restrict__ idx,
                          const float* __restrict__ sv, const float* __restrict__ bv,
                          float* __restrict__ out, int ldo)
{
    __shared__ int nb[20];
    int r = blockIdx.x;
    int base = (r >> 12) << 12;
    int tid = threadIdx.x;
    if (tid < 20) nb[tid] = idx[(long)r * 20 + tid];
    __syncthreads();
    for (int o = tid; o < O; o += blockDim.x) {
        float m = -FLT_MAX;
#pragma unroll
        for (int kk = 0; kk < 20; kk++)
            m = fmaxf(m, q[(long)(base + nb[kk]) * O + o]);
        float v = sv[o] * (m + p[(long)r * O + o]) + bv[o];
        out[(long)r * ldo + o] = lrelu(v);
    }
}

// ---------------- global max over N (two-pass) ----------------
__global__ void gmax1_k(const float* __restrict__ emb, float* __restrict__ part)
{
    int b = blockIdx.x >> 4, sp = blockIdx.x & 15;
    int o = blockIdx.y * 256 + threadIdx.x;
    const float* e = emb + ((long)b * 4096 + (long)sp * 256) * 1024 + o;
    float m = -FLT_MAX;
    for (int n = 0; n < 256; n++) m = fmaxf(m, e[(long)n * 1024]);
    part[(long)blockIdx.x * 1024 + o] = m;
}
__global__ void gmax2_k(const float* __restrict__ part, float* __restrict__ glob)
{
    int b = blockIdx.x; int o = blockIdx.y * 256 + threadIdx.x;
    float m = -FLT_MAX;
    for (int sp = 0; sp < 16; sp++) m = fmaxf(m, part[(long)(b * 16 + sp) * 1024 + o]);
    glob[(long)b * 1024 + o] = m;
}

// ---------------- host helpers ----------------
static void gemm(int mode,
                 const float* X, int ldx, long xbs,
                 const float* W, int ldw, long wbs,
                 float* Y, int ldy, long ybs,
                 int M, int K, int NO, int Z,
                 const float* sv, const float* bv,
                 const float* aux, int auxS)
{
    dim3 grid((NO + 63) / 64, (M + 63) / 64, Z);
    switch (mode) {
    case 0: gemm_k<0><<<grid, 256>>>(X, ldx, xbs, W, ldw, wbs, Y, ldy, ybs, M, K, NO, sv, bv, aux, auxS); break;
    case 1: gemm_k<1><<<grid, 256>>>(X, ldx, xbs, W, ldw, wbs, Y, ldy, ybs, M, K, NO, sv, bv, aux, auxS); break;
    case 2: gemm_k<2><<<grid, 256>>>(X, ldx, xbs, W, ldw, wbs, Y, ldy, ybs, M, K, NO, sv, bv, aux, auxS); break;
    case 3: gemm_k<3><<<grid, 256>>>(X, ldx, xbs, W, ldw, wbs, Y, ldy, ybs, M, K, NO, sv, bv, aux, auxS); break;
    case 4: gemm_k<4><<<grid, 256>>>(X, ldx, xbs, W, ldw, wbs, Y, ldy, ybs, M, K, NO, sv, bv, aux, auxS); break;
    }
}

extern "C" void kernel_launch(void* const* d_in, const int* in_sizes, int n_in,
                              void* d_out, int out_size)
{
    (void)in_sizes; (void)n_in;
    const float* xyz = (const float*)d_in[0];
    // d_in[1] is k (always 20)
    const float* w1 = (const float*)d_in[2];  const float* s1 = (const float*)d_in[3];  const float* b1 = (const float*)d_in[4];
    const float* w2 = (const float*)d_in[5];  const float* s2 = (const float*)d_in[6];  const float* b2 = (const float*)d_in[7];
    const float* w3 = (const float*)d_in[8];  const float* s3 = (const float*)d_in[9];  const float* b3 = (const float*)d_in[10];
    const float* w4 = (const float*)d_in[11]; const float* s4 = (const float*)d_in[12]; const float* b4 = (const float*)d_in[13];
    const float* wf = (const float*)d_in[14]; const float* sf = (const float*)d_in[15]; const float* bf = (const float*)d_in[16];
    const float* we = (const float*)d_in[17]; const float* se = (const float*)d_in[18]; const float* be = (const float*)d_in[19];
    const float* wh1 = (const float*)d_in[20]; const float* sh1 = (const float*)d_in[21]; const float* bh1 = (const float*)d_in[22];
    const float* wh2 = (const float*)d_in[23]; const float* sh2 = (const float*)d_in[24]; const float* bh2 = (const float*)d_in[25];
    const float* wh3 = (const float*)d_in[26]; const float* bh3 = (const float*)d_in[27];
    float* out = (float*)d_out;

    float *gd, *gcat, *gq, *gp, *gx2, *glocal, *gemb, *gpart, *gglob, *ggh, *gh1, *gh2, *gwd;
    int *gidx;
    cudaGetSymbolAddress((void**)&gd, g_d);
    cudaGetSymbolAddress((void**)&gcat, g_cat);
    cudaGetSymbolAddress((void**)&gq, g_q);
    cudaGetSymbolAddress((void**)&gp, g_p);
    cudaGetSymbolAddress((void**)&gx2, g_x2);
    cudaGetSymbolAddress((void**)&gidx, g_idx);
    cudaGetSymbolAddress((void**)&glocal, g_local);
    cudaGetSymbolAddress((void**)&gemb, g_emb);
    cudaGetSymbolAddress((void**)&gpart, g_part);
    cudaGetSymbolAddress((void**)&gglob, g_glob);
    cudaGetSymbolAddress((void**)&ggh, g_gh);
    cudaGetSymbolAddress((void**)&gh1, g_h1);
    cudaGetSymbolAddress((void**)&gh2, g_h2);
    cudaGetSymbolAddress((void**)&gwd, g_wd);

    const int B = 4, N = 4096, M = B * N;

    // one EdgeConv layer
    auto edge_layer = [&](const float* X, int ldx, int C,
                          const float* w, const float* sv, const float* bv,
                          int O, float* outCol) {
        // KNN: dist matrix + topk
        wdiff_k<<<(O * C + 255) / 256, 256>>>(w, C, O, gwd);
        sqnorm_k<<<M / 8, 256>>>(X, ldx, C, gx2);
        gemm(2, X, ldx, (long)N * ldx, X, ldx, (long)N * ldx,
             gd, N, (long)N * N, N, C, N, B, nullptr, nullptr, gx2, N);
        topk_k<<<M, 128>>>(gd, gidx);
        // q = X * w1^T, p = X * (w2-w1)^T
        gemm(0, X, ldx, 0, w, 2 * C, 0, gq, O, 0, M, C, O, 1, nullptr, nullptr, nullptr, 0);
        gemm(0, X, ldx, 0, gwd, C, 0, gp, O, 0, M, C, O, 1, nullptr, nullptr, nullptr, 0);
        combine_k<<<M, 128>>>(gq, gp, O, gidx, sv, bv, outCol, 512);
    };

    edge_layer(xyz,        3,   3,   w1, s1, b1, 64,  gcat + 0);
    edge_layer(gcat + 0,   512, 64,  w2, s2, b2, 64,  gcat + 64);
    edge_layer(gcat + 64,  512, 64,  w3, s3, b3, 128, gcat + 128);
    edge_layer(gcat + 128, 512, 128, w4, s4, b4, 256, gcat + 256);

    // x_local = leaky(cat * wf^T * sf + bf)
    gemm(1, gcat, 512, 0, wf, 512, 0, glocal, 512, 0, M, 512, 512, 1, sf, bf, nullptr, 0);
    // x_emb = leaky(local * we^T * se + be)
    gemm(1, glocal, 512, 0, we, 512, 0, gemb, 1024, 0, M, 512, 1024, 1, se, be, nullptr, 0);
    // global max over N
    { dim3 g1(64, 4); gmax1_k<<<g1, 256>>>(gemb, gpart); }
    { dim3 g2(4, 4);  gmax2_k<<<g2, 256>>>(gpart, gglob); }
    // G[b][o] = glob * wh1[:,512:]^T
    gemm(0, gglob, 1024, 0, wh1 + 512, 1536, 0, ggh, 256, 0, B, 1024, 256, 1, nullptr, nullptr, nullptr, 0);
    // h1 = leaky(sh1*(local*wh1[:,:512]^T + G[b]) + bh1)
    gemm(3, glocal, 512, 0, wh1, 1536, 0, gh1, 256, 0, M, 512, 256, 1, sh1, bh1, ggh, 256);
    // h2 = leaky(h1*wh2^T * sh2 + bh2)
    gemm(1, gh1, 256, 0, wh2, 256, 0, gh2, 256, 0, M, 256, 256, 1, sh2, bh2, nullptr, 0);
    // logits = h2*wh3^T + bh3
    gemm(4, gh2, 256, 0, wh3, 256, 0, out, 50, 0, M, 256, 50, 1, nullptr, bh3, nullptr, 0);
    (void)out_size;
}